// round 12
// baseline (speedup 1.0000x reference)
#include <cuda_runtime.h>

// TemporalDecay: out = h + (1-M)*gamma*(h_fwd - h), gamma = exp(-relu(delta*W + b))
// h_fwd[b,t,j] = h[b, t-(delta-1), j], delta in {1..4} clamped to t+1, d = j % 64.
//
// R11 = R10 (d-pair per thread, 8 outputs via float2, uniform delta/M per d,
// stride-1 predicated gathers, __ldcs/__stcs) with the k-loop split into TWO
// PASSES of 2 k's each to halve peak live registers:
//   regs 40 -> ~32  => 8 blocks/SM (2048 thr) instead of 6  => occ ~78%.
// Each pass still batches 8+ independent loads (ample MLP).

#define B_    32
#define T_    2048
#define D_    64
#define KD_   256
#define TPB   256
#define NTHR  (B_ * T_ * D_ / 2)   // 2,097,152 threads (one d-pair each)

__global__ __launch_bounds__(TPB, 8)
void temporal_decay_kernel(const float*  __restrict__ h,
                           const float2* __restrict__ h2,
                           const float2* __restrict__ dlt2,
                           const float2* __restrict__ m2,
                           const float2* __restrict__ w2,
                           const float2* __restrict__ b2,
                           float2* __restrict__ out2)
{
    const int i   = blockIdx.x * TPB + threadIdx.x;
    const int p   = i & 31;              // d-pair index: d = 2p
    const int row = i >> 5;              // b*T + t

    // ---- small uniform operands ----
    const float2 df = __ldcs(dlt2 + (row << 5) + p);
    const float2 mf = __ldcs(m2   + (row << 5) + p);

    const int dix = (int)df.x, diy = (int)df.y;
    const float ax = 1.0f - mf.x, ay = 1.0f - mf.y;
    const bool needx = (mf.x == 0.0f) && (dix > 1);
    const bool needy = (mf.y == 0.0f) && (diy > 1);

    const int base   = (row << 8) + (p << 1);          // scalar index, k=0, lane d
    const int gbasex = base - ((dix - 1) << 8);
    const int gbasey = base + 1 - ((diy - 1) << 8);

    // ---- two passes of k = {k0, k0+1}: halved live-register footprint ----
    #pragma unroll
    for (int k0 = 0; k0 < 4; k0 += 2) {
        const float2 wwa = w2[(k0 << 5) + p];
        const float2 bba = b2[(k0 << 5) + p];
        const float2 wwb = w2[((k0 + 1) << 5) + p];
        const float2 bbb = b2[((k0 + 1) << 5) + p];

        const float2 haa = h2[(base >> 1) + (k0 << 5)];
        const float2 hab = h2[(base >> 1) + ((k0 + 1) << 5)];

        const float fxa = needx ? __ldg(h + gbasex + (k0 << 6))       : haa.x;
        const float fya = needy ? __ldg(h + gbasey + (k0 << 6))       : haa.y;
        const float fxb = needx ? __ldg(h + gbasex + ((k0 + 1) << 6)) : hab.x;
        const float fyb = needy ? __ldg(h + gbasey + ((k0 + 1) << 6)) : hab.y;

        const float cxa = ax * fminf(__expf(-fmaf(df.x, wwa.x, bba.x)), 1.0f);
        const float cya = ay * fminf(__expf(-fmaf(df.y, wwa.y, bba.y)), 1.0f);
        const float cxb = ax * fminf(__expf(-fmaf(df.x, wwb.x, bbb.x)), 1.0f);
        const float cyb = ay * fminf(__expf(-fmaf(df.y, wwb.y, bbb.y)), 1.0f);

        float2 oa, ob;
        oa.x = fmaf(cxa, fxa - haa.x, haa.x);
        oa.y = fmaf(cya, fya - haa.y, haa.y);
        ob.x = fmaf(cxb, fxb - hab.x, hab.x);
        ob.y = fmaf(cyb, fyb - hab.y, hab.y);

        __stcs(out2 + (base >> 1) + (k0 << 5), oa);
        __stcs(out2 + (base >> 1) + ((k0 + 1) << 5), ob);
    }
}

extern "C" void kernel_launch(void* const* d_in, const int* in_sizes, int n_in,
                              void* d_out, int out_size)
{
    const float* h_a    = (const float*)d_in[0];
    const float* deltas = (const float*)d_in[1];
    const float* M      = (const float*)d_in[2];
    const float* W      = (const float*)d_in[3];
    const float* bvec   = (const float*)d_in[4];
    float* out          = (float*)d_out;

    const int blocks = NTHR / TPB;   // 8192

    temporal_decay_kernel<<<blocks, TPB>>>(
        h_a, (const float2*)h_a,
        (const float2*)deltas, (const float2*)M,
        (const float2*)W, (const float2*)bvec,
        (float2*)out);
}

// round 13
// speedup vs baseline: 1.0021x; 1.0021x over previous
#include <cuda_runtime.h>
#include <cuda_pipeline.h>

// TemporalDecay: out = h + (1-M)*gamma*(h_fwd - h), gamma = exp(-relu(delta*W + b))
// h_fwd[b,t,j] = h[b, t-(delta-1), j], delta in {1..4} clamped to t+1, d = j % 64.
//
// R12: d-pair mapping (R10) + block-level shared-memory staging of h.
// Block = 8 consecutive rows (8 warps, warp w owns row r0+w). Stage rows
// r0-3 .. r0+7 (11 rows, 11.25KB) into smem via cp.async; own-reads and the
// delta-gathers then come from smem, so h passes L1tex 1.4x instead of ~4x
// and every global access is a full 128B line.
//  * pre-barrier phase does ALL global loads (staging + delta/M/W/b) and the
//    coef math -> no idle prologue (R9's mistake).
//  * delta-clamp (delta <= t+1) guarantees halo rows of t0==0 blocks are never
//    read; staging source clamped at row 0 for OOB safety only.
//  * __ldcs on delta/M, __stcs on out kept from R8/R10.

#define B_      32
#define T_      2048
#define KD_     256
#define TPB     256
#define ROWS_PB 8
#define HALO    3
#define SROWS   (ROWS_PB + HALO)     // 11
#define NBLK    (B_ * T_ / ROWS_PB)  // 8192

__global__ __launch_bounds__(TPB, 6)
void temporal_decay_kernel(const float*  __restrict__ h,
                           const float2* __restrict__ dlt2,
                           const float2* __restrict__ m2,
                           const float2* __restrict__ w2,
                           const float2* __restrict__ b2,
                           float2* __restrict__ out2)
{
    __shared__ float sh[SROWS * KD_];   // 11.25 KB

    const int tid = threadIdx.x;
    const int r0  = blockIdx.x * ROWS_PB;   // global first row of block
    const int src0 = r0 - HALO;

    // ---- stage 11 rows via cp.async (704 x 16B chunks, 2.75 per thread) ----
    for (int idx = tid; idx < SROWS * (KD_ / 4); idx += TPB) {
        const int rel  = idx >> 6;               // smem row 0..10
        const int srow = max(src0 + rel, 0);     // OOB guard (b=0,t0=0 only)
        __pipeline_memcpy_async(
            (float4*)sh + idx,
            (const float4*)h + (size_t)srow * (KD_ / 4) + (idx & 63),
            16);
    }
    __pipeline_commit();

    // ---- overlap: small operands + coef math while staging is in flight ----
    const int p    = tid & 31;        // d-pair index, d = 2p
    const int wrow = tid >> 5;        // 0..7
    const int row  = r0 + wrow;

    const float2 df = __ldcs(dlt2 + (row << 5) + p);
    const float2 mf = __ldcs(m2   + (row << 5) + p);

    const int dix = (int)df.x, diy = (int)df.y;
    const float ax = 1.0f - mf.x, ay = 1.0f - mf.y;
    const bool needx = (mf.x == 0.0f) && (dix > 1);
    const bool needy = (mf.y == 0.0f) && (diy > 1);

    float cx[4], cy[4];
    #pragma unroll
    for (int k = 0; k < 4; ++k) {
        const float2 ww = w2[(k << 5) + p];
        const float2 bb = b2[(k << 5) + p];
        cx[k] = ax * fminf(__expf(-fmaf(df.x, ww.x, bb.x)), 1.0f);
        cy[k] = ay * fminf(__expf(-fmaf(df.y, ww.y, bb.y)), 1.0f);
    }

    __pipeline_wait_prior(0);
    __syncthreads();

    // ---- compute from smem ----
    const int rel  = wrow + HALO;            // own smem row (3..10)
    const int relx = rel - (dix - 1);        // gather smem rows (>=0 by clamp)
    const int rely = rel - (diy - 1);
    const int dofs = p << 1;

    const float* so  = sh + rel  * KD_ + dofs;
    const float* sgx = sh + relx * KD_ + dofs;
    const float* sgy = sh + rely * KD_ + dofs + 1;

    const int obase = (row << 7) + p;        // float2 index: row*128 + k*32 + p

    #pragma unroll
    for (int k = 0; k < 4; ++k) {
        const float2 ho = *(const float2*)(so + (k << 6));
        const float  fx = needx ? sgx[k << 6] : ho.x;
        const float  fy = needy ? sgy[k << 6] : ho.y;
        float2 o;
        o.x = fmaf(cx[k], fx - ho.x, ho.x);
        o.y = fmaf(cy[k], fy - ho.y, ho.y);
        __stcs(out2 + obase + (k << 5), o);
    }
}

extern "C" void kernel_launch(void* const* d_in, const int* in_sizes, int n_in,
                              void* d_out, int out_size)
{
    const float* h_a    = (const float*)d_in[0];
    const float* deltas = (const float*)d_in[1];
    const float* M      = (const float*)d_in[2];
    const float* W      = (const float*)d_in[3];
    const float* bvec   = (const float*)d_in[4];
    float* out          = (float*)d_out;

    temporal_decay_kernel<<<NBLK, TPB>>>(
        h_a,
        (const float2*)deltas, (const float2*)M,
        (const float2*)W, (const float2*)bvec,
        (float2*)out);
}